// round 1
// baseline (speedup 1.0000x reference)
#include <cuda_runtime.h>
#include <math.h>

// Combined weight table: for pixel p (row-major 28x28) and class k:
//   g_w2[k*784+p] = ( w[k,f]*alpha_c , w[k,f]*beta_c )
// where f is the patch-flattened feature index of pixel p and c its channel.
__device__ float2 g_w2[7840];

// ---------------------------------------------------------------------------
// Kernel A: compute per-channel SU(2) coefficients and fold into weights.
// ---------------------------------------------------------------------------
__global__ void coef_kernel(const float* __restrict__ params,
                            const float* __restrict__ w) {
    __shared__ float s_alpha[4];
    __shared__ float s_beta[4];
    int tid = threadIdx.x;
    if (tid < 4) {
        int c = tid;
        // U = I (complex 2x2, row-major): u00, u01, u10, u11
        float u00r = 1.f, u00i = 0.f, u01r = 0.f, u01i = 0.f;
        float u10r = 0.f, u10i = 0.f, u11r = 1.f, u11i = 0.f;
        for (int d = 0; d < 4; d++) {
            float rz1 = params[(d * 4 + c) * 3 + 0];
            float ry  = params[(d * 4 + c) * 3 + 1];
            float rz2 = params[(d * 4 + c) * 3 + 2];
            // Rz(rz1): row0 *= e^{-i rz1/2}, row1 *= e^{+i rz1/2}
            {
                float ph = 0.5f * rz1;
                float cr = cosf(ph), ci = -sinf(ph);        // e^{-i ph}
                float t;
                t = u00r * cr - u00i * ci; u00i = u00r * ci + u00i * cr; u00r = t;
                t = u01r * cr - u01i * ci; u01i = u01r * ci + u01i * cr; u01r = t;
                t = u10r * cr + u10i * ci; u10i = -u10r * ci + u10i * cr; u10r = t;
                t = u11r * cr + u11i * ci; u11i = -u11r * ci + u11i * cr; u11r = t;
            }
            // Ry(ry): row0' = c*row0 - s*row1 ; row1' = s*row0 + c*row1
            {
                float cc = cosf(0.5f * ry), ss = sinf(0.5f * ry);
                float n00r = cc * u00r - ss * u10r, n00i = cc * u00i - ss * u10i;
                float n01r = cc * u01r - ss * u11r, n01i = cc * u01i - ss * u11i;
                float n10r = ss * u00r + cc * u10r, n10i = ss * u00i + cc * u10i;
                float n11r = ss * u01r + cc * u11r, n11i = ss * u01i + cc * u11i;
                u00r = n00r; u00i = n00i; u01r = n01r; u01i = n01i;
                u10r = n10r; u10i = n10i; u11r = n11r; u11i = n11i;
            }
            // Rz(rz2)
            {
                float ph = 0.5f * rz2;
                float cr = cosf(ph), ci = -sinf(ph);
                float t;
                t = u00r * cr - u00i * ci; u00i = u00r * ci + u00i * cr; u00r = t;
                t = u01r * cr - u01i * ci; u01i = u01r * ci + u01i * cr; u01r = t;
                t = u10r * cr + u10i * ci; u10i = -u10r * ci + u10i * cr; u10r = t;
                t = u11r * cr + u11i * ci; u11i = -u11r * ci + u11i * cr; u11r = t;
            }
        }
        // M = U^dag sigma_z U:
        //   alpha = M00 = |U00|^2 - |U10|^2
        //   beta  = Re(M01) = Re(conj(U00)U01 - conj(U10)U11)
        s_alpha[c] = (u00r * u00r + u00i * u00i) - (u10r * u10r + u10i * u10i);
        s_beta[c]  = (u00r * u01r + u00i * u01i) - (u10r * u11r + u10i * u11i);
    }
    __syncthreads();
    for (int idx = tid; idx < 7840; idx += blockDim.x) {
        int k = idx / 784;
        int p = idx - k * 784;
        int r  = p / 28, cc = p - r * 28;
        int i  = r >> 1, di = r & 1;
        int j  = cc >> 1, dj = cc & 1;
        int ch = di * 2 + dj;
        int f  = (i * 14 + j) * 4 + ch;
        float wv = w[k * 784 + f];
        g_w2[idx] = make_float2(wv * s_alpha[ch], wv * s_beta[ch]);
    }
}

// ---------------------------------------------------------------------------
// Kernel B: per warp, 4 batch rows. Shared-mem weight table [k][p] (float2),
// coalesced LDG of x, MUFU sincos, 80 FMA/iter, warp butterfly reduce,
// fused log-softmax.
// ---------------------------------------------------------------------------
#define ROWS_PER_WARP 4
#define NTASKS (8192 / ROWS_PER_WARP)

__global__ __launch_bounds__(256, 2)
void quanv_main_kernel(const float* __restrict__ x,
                       const float* __restrict__ bias,
                       float* __restrict__ out) {
    extern __shared__ float2 sw[];   // 7840 float2 = 62720 B, layout [k][p]
    __shared__ float sb[10];

    for (int i = threadIdx.x; i < 7840; i += blockDim.x)
        sw[i] = g_w2[i];
    if (threadIdx.x < 10)
        sb[threadIdx.x] = bias[threadIdx.x];
    __syncthreads();

    const int warp  = threadIdx.x >> 5;
    const int lane  = threadIdx.x & 31;
    const int nwarp = (gridDim.x * blockDim.x) >> 5;
    int task = blockIdx.x * (blockDim.x >> 5) + warp;

    for (; task < NTASKS; task += nwarp) {
        const int row0 = task * ROWS_PER_WARP;
        const float* xp = x + (size_t)row0 * 784;

        float acc[ROWS_PER_WARP][10];
#pragma unroll
        for (int r = 0; r < ROWS_PER_WARP; r++)
#pragma unroll
            for (int k = 0; k < 10; k++) acc[r][k] = 0.f;

#pragma unroll 5
        for (int t = 0; t < 25; t++) {
            int p = t * 32 + lane;
            bool valid = (p < 784);
            int pc = valid ? p : 0;
            float cs[ROWS_PER_WARP], sn[ROWS_PER_WARP];
#pragma unroll
            for (int r = 0; r < ROWS_PER_WARP; r++) {
                float v = valid ? __ldg(xp + r * 784 + pc) : 0.f;
                float s, c;
                __sincosf(v, &s, &c);
                sn[r] = valid ? s : 0.f;
                cs[r] = valid ? c : 0.f;
            }
#pragma unroll
            for (int k = 0; k < 10; k++) {
                float2 wv = sw[k * 784 + pc];
#pragma unroll
                for (int r = 0; r < ROWS_PER_WARP; r++)
                    acc[r][k] = fmaf(cs[r], wv.x, fmaf(sn[r], wv.y, acc[r][k]));
            }
        }

#pragma unroll
        for (int r = 0; r < ROWS_PER_WARP; r++) {
            float l[10];
#pragma unroll
            for (int k = 0; k < 10; k++) {
                float v = acc[r][k];
                v += __shfl_xor_sync(0xFFFFFFFFu, v, 16);
                v += __shfl_xor_sync(0xFFFFFFFFu, v, 8);
                v += __shfl_xor_sync(0xFFFFFFFFu, v, 4);
                v += __shfl_xor_sync(0xFFFFFFFFu, v, 2);
                v += __shfl_xor_sync(0xFFFFFFFFu, v, 1);
                l[k] = v + sb[k];
            }
            float m = l[0];
#pragma unroll
            for (int k = 1; k < 10; k++) m = fmaxf(m, l[k]);
            float sum = 0.f;
#pragma unroll
            for (int k = 0; k < 10; k++) sum += expf(l[k] - m);
            float lse = m + logf(sum);
            float myv = 0.f;
#pragma unroll
            for (int k = 0; k < 10; k++)
                if (lane == k) myv = l[k] - lse;
            if (lane < 10)
                out[(size_t)(row0 + r) * 10 + lane] = myv;
        }
    }
}

extern "C" void kernel_launch(void* const* d_in, const int* in_sizes, int n_in,
                              void* d_out, int out_size) {
    const float* x      = (const float*)d_in[0];   // (8192,1,28,28)
    const float* params = (const float*)d_in[1];   // (4,4,3)
    const float* w      = (const float*)d_in[2];   // (10,784)
    const float* bias   = (const float*)d_in[3];   // (10,)
    float* out          = (float*)d_out;           // (8192,10)

    static bool attr_set = false;
    // Deterministic, host-side only, no device work: safe to do every call,
    // but setting the attribute is idempotent anyway.
    cudaFuncSetAttribute(quanv_main_kernel,
                         cudaFuncAttributeMaxDynamicSharedMemorySize,
                         7840 * sizeof(float2) + 1024);
    (void)attr_set;

    coef_kernel<<<1, 256>>>(params, w);
    quanv_main_kernel<<<296, 256, 7840 * sizeof(float2)>>>(x, bias, out);
}